// round 1
// baseline (speedup 1.0000x reference)
#include <cuda_runtime.h>
#include <math.h>
#include <float.h>

// Problem constants (fixed by the dataset)
#define BB   256      // batch
#define CC   128      // embedding dim C
#define KK   4096     // negatives per sample
#define NCLSS 100     // n classes
#define KNNK 8
#define INV_T 14.285714285714286f   // 1/0.07
#define LSE_SHIFT 25.0f             // hard bound: |dot|<=1.733, /T <= 24.8

// ---------------- scratch (device globals; no allocation allowed) ----------
__device__ __align__(16) float g_fes[BB*CC];
__device__ __align__(16) float g_fet[BB*CC];
__device__ __align__(16) float g_fgs[BB*CC];
__device__ __align__(16) float g_fgt[BB*CC];
__device__ __align__(16) float g_u[2*BB*NCLSS];   // normalized softmax rows (soft/||soft||)
__device__ int   g_nbr[2*BB*KNNK];
__device__ float g_pos[4*BB];    // 0:ls 1:lt 2:gs 3:gt
__device__ float g_term[4*BB];   // lse - pos/T per stream per b

// ---------------- embed: f_e = l2norm(x @ W^T + b) --------------------------
// One CTA handles ROWS batch rows; thread c owns output channel c.
template<int D, int ROWS>
__global__ __launch_bounds__(128) void embed_kernel(const float* __restrict__ x,
        const float* __restrict__ W, const float* __restrict__ bias)
{
    __shared__ float xs[ROWS*D];
    __shared__ float red[CC];
    float* out = (D == 1024) ? g_fes : g_fet;
    const int c = threadIdx.x;
    const int g = blockIdx.x;
    const float* xrow = x + (size_t)g*ROWS*D;
    for (int t = c; t < ROWS*D; t += 128) xs[t] = xrow[t];
    __syncthreads();

    float acc[ROWS];
    #pragma unroll
    for (int r = 0; r < ROWS; r++) acc[r] = 0.f;

    const float4* w4 = (const float4*)(W + (size_t)c*D);
    #pragma unroll 4
    for (int i = 0; i < D/4; i++) {
        float4 w = w4[i];
        #pragma unroll
        for (int r = 0; r < ROWS; r++) {
            float4 xv = ((const float4*)(xs + r*D))[i];
            acc[r] += w.x*xv.x + w.y*xv.y + w.z*xv.z + w.w*xv.w;
        }
    }
    float bv = bias[c];
    #pragma unroll
    for (int r = 0; r < ROWS; r++) acc[r] += bv;

    for (int r = 0; r < ROWS; r++) {
        red[c] = acc[r]*acc[r];
        __syncthreads();
        for (int off = 64; off > 0; off >>= 1) {
            if (c < off) red[c] += red[c+off];
            __syncthreads();
        }
        float inv = rsqrtf(red[0]);
        __syncthreads();
        out[(size_t)(g*ROWS + r)*CC + c] = acc[r]*inv;
    }
}

// ---------------- softmax rows, normalized: u = e / ||e|| -------------------
// sim(i,j) = soft_i.soft_j/(w_i w_j) == u_i.u_j (the 1/sum factors cancel).
__global__ __launch_bounds__(128) void soft_kernel(const float* __restrict__ ls,
                                                   const float* __restrict__ lt)
{
    const int b = blockIdx.x, which = blockIdx.y;
    const float* l = (which ? lt : ls) + (size_t)b*NCLSS;
    float* u = g_u + ((size_t)which*BB + b)*NCLSS;
    const int t = threadIdx.x;
    __shared__ float red[128];

    float v = (t < NCLSS) ? l[t] : -FLT_MAX;
    red[t] = v; __syncthreads();
    for (int off = 64; off > 0; off >>= 1) { if (t < off) red[t] = fmaxf(red[t], red[t+off]); __syncthreads(); }
    float mx = red[0]; __syncthreads();

    float e = (t < NCLSS) ? expf(v - mx) : 0.f;
    red[t] = e*e; __syncthreads();
    for (int off = 64; off > 0; off >>= 1) { if (t < off) red[t] += red[t+off]; __syncthreads(); }
    float inv = rsqrtf(red[0]);
    if (t < NCLSS) u[t] = e*inv;
}

// ---------------- knn: top-8 of (-dist), self forced first ------------------
__global__ __launch_bounds__(256) void knn_kernel()
{
    const int i = blockIdx.x, which = blockIdx.y;
    const float* u = g_u + (size_t)which*BB*NCLSS;
    const int t = threadIdx.x;
    __shared__ float ui[NCLSS];
    __shared__ float val[BB];
    __shared__ float rv[BB];
    __shared__ int   ri[BB];

    if (t < NCLSS) ui[t] = u[(size_t)i*NCLSS + t];
    __syncthreads();
    {
        const float* uj = u + (size_t)t*NCLSS;
        float d = 0.f;
        for (int e = 0; e < NCLSS; e++) d += ui[e]*uj[e];
        val[t] = (t == i) ? 1.0f : (d - 1.0f);  // = -dist
    }
    __syncthreads();

    for (int r = 0; r < KNNK; r++) {
        rv[t] = val[t]; ri[t] = t; __syncthreads();
        for (int off = 128; off > 0; off >>= 1) {
            if (t < off) {
                float ov = rv[t+off]; int oi = ri[t+off];
                if (ov > rv[t] || (ov == rv[t] && oi < ri[t])) { rv[t] = ov; ri[t] = oi; }
            }
            __syncthreads();
        }
        if (t == 0) { g_nbr[((size_t)which*BB + i)*KNNK + r] = ri[0]; val[ri[0]] = -FLT_MAX; }
        __syncthreads();
    }
}

// ---------------- gnn_encode: l2norm(concat(h, mean(h[nbr])) @ W + b) -------
__global__ __launch_bounds__(128) void gnn_kernel(const float* __restrict__ Wgs, const float* __restrict__ bgs,
                                                  const float* __restrict__ Wgt, const float* __restrict__ bgt)
{
    const int b = blockIdx.x, which = blockIdx.y;
    const float* fe  = which ? g_fet : g_fes;
    const float* W   = which ? Wgt : Wgs;
    const float* bias= which ? bgt : bgs;
    float* fg        = which ? g_fgt : g_fgs;
    const int* nbr = g_nbr + ((size_t)which*BB + b)*KNNK;
    const int c = threadIdx.x;
    __shared__ float h2[2*CC];
    __shared__ float red[CC];
    __shared__ int nb[KNNK];

    if (c < KNNK) nb[c] = nbr[c];
    h2[c] = fe[(size_t)b*CC + c];
    __syncthreads();
    float agg = 0.f;
    #pragma unroll
    for (int q = 0; q < KNNK; q++) agg += fe[(size_t)nb[q]*CC + c];
    h2[CC + c] = agg * (1.0f/KNNK);
    __syncthreads();

    float acc = bias[c];
    #pragma unroll 4
    for (int r = 0; r < 2*CC; r++) acc += h2[r] * W[(size_t)r*CC + c];

    red[c] = acc*acc; __syncthreads();
    for (int off = 64; off > 0; off >>= 1) { if (c < off) red[c] += red[c+off]; __syncthreads(); }
    fg[(size_t)b*CC + c] = acc * rsqrtf(red[0]);
}

// ---------------- smooth + positive logits ---------------------------------
__device__ __forceinline__ float breduce128(float v, float* red, int c)
{
    red[c] = v; __syncthreads();
    for (int off = 64; off > 0; off >>= 1) { if (c < off) red[c] += red[c+off]; __syncthreads(); }
    float r = red[0]; __syncthreads();
    return r;
}

__global__ __launch_bounds__(128) void smooth_pos_kernel(const int* __restrict__ idx,
        const float* __restrict__ mem_l, const float* __restrict__ mem_ab)
{
    const int b = blockIdx.x, c = threadIdx.x;
    __shared__ float red[CC];
    const int id = idx[b];
    float ml  = mem_l [(size_t)id*CC + c];
    float mab = mem_ab[(size_t)id*CC + c];
    float fes = g_fes[(size_t)b*CC + c], fet = g_fet[(size_t)b*CC + c];
    float fgs = g_fgs[(size_t)b*CC + c], fgt = g_fgt[(size_t)b*CC + c];

    float sgs = ml *0.75f + fgs*0.25f;   // f_sgs pre-norm
    float sgt = mab*0.75f + fgt*0.25f;   // f_sgt pre-norm
    sgs *= rsqrtf(breduce128(sgs*sgs, red, c));
    sgt *= rsqrtf(breduce128(sgt*sgt, red, c));

    float ls = breduce128(mab*fes, red, c);  // ls_pos = f_ut . f_es
    float lt = breduce128(ml *fet, red, c);  // lt_pos = f_us . f_et
    float gs = breduce128(sgt*fgs, red, c);  // gs_pos = f_sgt . f_gs
    float gt = breduce128(sgs*fgt, red, c);  // gt_pos = f_sgs . f_gt
    if (c == 0) {
        g_pos[0*BB+b] = ls; g_pos[1*BB+b] = lt;
        g_pos[2*BB+b] = gs; g_pos[3*BB+b] = gt;
    }
}

// ---------------- heavy kernel: gathered dual-GEMV + fixed-shift LSE --------
// grid (256, 2). bank 0: mem_l  x (f_es -> stream0, f_gs -> stream2)
//                bank 1: mem_ab x (f_et -> stream1, f_gt -> stream3)
__global__ __launch_bounds__(256) void neg_kernel(const int* __restrict__ cidx,
        const float* __restrict__ mem_l, const float* __restrict__ mem_ab)
{
    const int b = blockIdx.x, bank = blockIdx.y;
    const float* mem = bank ? mem_ab : mem_l;
    const float* v1p = (bank ? g_fet : g_fes) + (size_t)b*CC;
    const float* v2p = (bank ? g_fgt : g_fgs) + (size_t)b*CC;
    const int t = threadIdx.x, w = t >> 5, lane = t & 31;

    const float4 a1 = *(const float4*)(v1p + lane*4);
    const float4 a2 = *(const float4*)(v2p + lane*4);
    const int* ci = cidx + (size_t)b*KK + w*(KK/8);

    float s1 = 0.f, s2 = 0.f;
    #pragma unroll 4
    for (int it = 0; it < KK/8; it++) {
        int r = ci[it];
        float4 x = *(const float4*)(mem + (size_t)r*CC + lane*4);
        float d1 = x.x*a1.x + x.y*a1.y + x.z*a1.z + x.w*a1.w;
        float d2 = x.x*a2.x + x.y*a2.y + x.z*a2.z + x.w*a2.w;
        #pragma unroll
        for (int o = 16; o; o >>= 1) {
            d1 += __shfl_xor_sync(0xffffffffu, d1, o);
            d2 += __shfl_xor_sync(0xffffffffu, d2, o);
        }
        s1 += __expf(fmaf(d1, INV_T, -LSE_SHIFT));
        s2 += __expf(fmaf(d2, INV_T, -LSE_SHIFT));
    }

    __shared__ float ss1[8], ss2[8];
    if (lane == 0) { ss1[w] = s1; ss2[w] = s2; }
    __syncthreads();
    if (t == 0) {
        const int st1 = bank;       // 0:ls, 1:lt
        const int st2 = 2 + bank;   // 2:gs, 3:gt
        float p1 = g_pos[st1*BB + b] * INV_T;
        float p2 = g_pos[st2*BB + b] * INV_T;
        float S1 = __expf(p1 - LSE_SHIFT);
        float S2 = __expf(p2 - LSE_SHIFT);
        #pragma unroll
        for (int q = 0; q < 8; q++) { S1 += ss1[q]; S2 += ss2[q]; }
        g_term[st1*BB + b] = LSE_SHIFT + logf(S1) - p1;
        g_term[st2*BB + b] = LSE_SHIFT + logf(S2) - p2;
    }
}

// ---------------- final reduce ----------------------------------------------
__global__ __launch_bounds__(256) void final_kernel(float* __restrict__ out)
{
    const int t = threadIdx.x;
    __shared__ float red[256];
    float v = g_term[t] + g_term[BB + t] + g_term[2*BB + t] + g_term[3*BB + t];
    red[t] = v; __syncthreads();
    for (int off = 128; off > 0; off >>= 1) { if (t < off) red[t] += red[t+off]; __syncthreads(); }
    if (t == 0) out[0] = red[0] * (1.0f/BB);
}

// ---------------- launch -----------------------------------------------------
extern "C" void kernel_launch(void* const* d_in, const int* in_sizes, int n_in,
                              void* d_out, int out_size)
{
    // metadata order: epoch, f_s, l_s, f_t, l_t, idx, contrast_idx,
    //                 W_es, b_es, W_et, b_et, W_gs, b_gs, W_gt, b_gt,
    //                 memory_l, memory_ab
    const float* f_s   = (const float*)d_in[1];
    const float* l_s   = (const float*)d_in[2];
    const float* f_t   = (const float*)d_in[3];
    const float* l_t   = (const float*)d_in[4];
    const int*   idx   = (const int*)  d_in[5];
    const int*   cidx  = (const int*)  d_in[6];
    const float* W_es  = (const float*)d_in[7];
    const float* b_es  = (const float*)d_in[8];
    const float* W_et  = (const float*)d_in[9];
    const float* b_et  = (const float*)d_in[10];
    const float* W_gs  = (const float*)d_in[11];
    const float* b_gs  = (const float*)d_in[12];
    const float* W_gt  = (const float*)d_in[13];
    const float* b_gt  = (const float*)d_in[14];
    const float* mem_l = (const float*)d_in[15];
    const float* mem_ab= (const float*)d_in[16];
    float* out = (float*)d_out;

    embed_kernel<1024, 8><<<BB/8, 128>>>(f_s, W_es, b_es);   // -> g_fes
    embed_kernel<2048, 4><<<BB/4, 128>>>(f_t, W_et, b_et);   // -> g_fet
    soft_kernel<<<dim3(BB, 2), 128>>>(l_s, l_t);             // -> g_u
    knn_kernel<<<dim3(BB, 2), 256>>>();                      // -> g_nbr
    gnn_kernel<<<dim3(BB, 2), 128>>>(W_gs, b_gs, W_gt, b_gt);// -> g_fgs/g_fgt
    smooth_pos_kernel<<<BB, 128>>>(idx, mem_l, mem_ab);      // -> g_pos
    neg_kernel<<<dim3(BB, 2), 256>>>(cidx, mem_l, mem_ab);   // -> g_term
    final_kernel<<<1, 256>>>(out);
}

// round 2
// speedup vs baseline: 1.2271x; 1.2271x over previous
#include <cuda_runtime.h>
#include <math.h>
#include <float.h>

// Problem constants (fixed by the dataset)
#define BB   256      // batch
#define CC   128      // embedding dim C
#define KK   4096     // negatives per sample
#define NCLSS 100     // n classes
#define KNNK 8
#define INV_T 14.285714285714286f   // 1/0.07
#define LSE_SHIFT 25.0f             // hard bound: |dot|<=1.733 -> /T <= 24.8

// ---------------- scratch (device globals; no allocation allowed) ----------
__device__ __align__(16) float g_fes[BB*CC];
__device__ __align__(16) float g_fet[BB*CC];
__device__ __align__(16) float g_fgs[BB*CC];
__device__ __align__(16) float g_fgt[BB*CC];
__device__ __align__(16) float g_u[2*BB*NCLSS];   // normalized softmax rows
__device__ int   g_nbr[2*BB*KNNK];
__device__ float g_pos[4*BB];    // 0:ls 1:lt 2:gs 3:gt
__device__ float g_term[4*BB];   // lse - pos/T per stream per b

// ---------------- embed: f_e = l2norm(x @ W^T + b) --------------------------
template<int D, int ROWS>
__global__ __launch_bounds__(128) void embed_kernel(const float* __restrict__ x,
        const float* __restrict__ W, const float* __restrict__ bias)
{
    __shared__ float xs[ROWS*D];
    __shared__ float red[CC];
    float* out = (D == 1024) ? g_fes : g_fet;
    const int c = threadIdx.x;
    const int g = blockIdx.x;
    const float* xrow = x + (size_t)g*ROWS*D;
    for (int t = c; t < ROWS*D; t += 128) xs[t] = xrow[t];
    __syncthreads();

    float acc[ROWS];
    #pragma unroll
    for (int r = 0; r < ROWS; r++) acc[r] = 0.f;

    const float4* w4 = (const float4*)(W + (size_t)c*D);
    #pragma unroll 4
    for (int i = 0; i < D/4; i++) {
        float4 w = w4[i];
        #pragma unroll
        for (int r = 0; r < ROWS; r++) {
            float4 xv = ((const float4*)(xs + r*D))[i];
            acc[r] += w.x*xv.x + w.y*xv.y + w.z*xv.z + w.w*xv.w;
        }
    }
    float bv = bias[c];
    #pragma unroll
    for (int r = 0; r < ROWS; r++) acc[r] += bv;

    for (int r = 0; r < ROWS; r++) {
        red[c] = acc[r]*acc[r];
        __syncthreads();
        for (int off = 64; off > 0; off >>= 1) {
            if (c < off) red[c] += red[c+off];
            __syncthreads();
        }
        float inv = rsqrtf(red[0]);
        __syncthreads();
        out[(size_t)(g*ROWS + r)*CC + c] = acc[r]*inv;
    }
}

// ---------------- softmax rows, normalized: u = e / ||e|| -------------------
__global__ __launch_bounds__(128) void soft_kernel(const float* __restrict__ ls,
                                                   const float* __restrict__ lt)
{
    const int b = blockIdx.x, which = blockIdx.y;
    const float* l = (which ? lt : ls) + (size_t)b*NCLSS;
    float* u = g_u + ((size_t)which*BB + b)*NCLSS;
    const int t = threadIdx.x;
    __shared__ float red[128];

    float v = (t < NCLSS) ? l[t] : -FLT_MAX;
    red[t] = v; __syncthreads();
    for (int off = 64; off > 0; off >>= 1) { if (t < off) red[t] = fmaxf(red[t], red[t+off]); __syncthreads(); }
    float mx = red[0]; __syncthreads();

    float e = (t < NCLSS) ? expf(v - mx) : 0.f;
    red[t] = e*e; __syncthreads();
    for (int off = 64; off > 0; off >>= 1) { if (t < off) red[t] += red[t+off]; __syncthreads(); }
    float inv = rsqrtf(red[0]);
    if (t < NCLSS) u[t] = e*inv;
}

// ---------------- knn: top-8 of (-dist), warp-register selection ------------
__global__ __launch_bounds__(128) void knn_kernel()
{
    const int i = blockIdx.x, which = blockIdx.y;
    const float* u = g_u + (size_t)which*BB*NCLSS;
    const int t = threadIdx.x, lane = t & 31;
    __shared__ float ui[NCLSS];
    __shared__ float val[BB];

    if (t < NCLSS) ui[t] = u[(size_t)i*NCLSS + t];
    __syncthreads();

    // each of 128 threads computes 2 candidate values
    #pragma unroll
    for (int p = 0; p < 2; p++) {
        int jj = t + 128*p;
        const float* uj = u + (size_t)jj*NCLSS;
        float d = 0.f;
        for (int e = 0; e < NCLSS; e++) d += ui[e]*uj[e];
        val[jj] = (jj == i) ? 1.0f : (d - 1.0f);  // = -dist
    }
    __syncthreads();

    if (t < 32) {
        // lane holds 8 candidates: global idx = lane + 32*q
        float v[8];
        #pragma unroll
        for (int q = 0; q < 8; q++) v[q] = val[lane + 32*q];

        for (int r = 0; r < KNNK; r++) {
            // local argmax (prefer larger val; tie -> smaller index)
            float bv = v[0]; int bq = 0;
            #pragma unroll
            for (int q = 1; q < 8; q++) if (v[q] > bv) { bv = v[q]; bq = q; }
            int bidx = lane + 32*bq;
            // warp argmax
            #pragma unroll
            for (int o = 16; o; o >>= 1) {
                float ov = __shfl_xor_sync(0xffffffffu, bv, o);
                int   oi = __shfl_xor_sync(0xffffffffu, bidx, o);
                if (ov > bv || (ov == bv && oi < bidx)) { bv = ov; bidx = oi; }
            }
            if (lane == 0) g_nbr[((size_t)which*BB + i)*KNNK + r] = bidx;
            // winner removes itself
            if (lane == (bidx & 31)) v[bidx >> 5] = -FLT_MAX;
        }
    }
}

// ---------------- gnn_encode: 4 batch rows per CTA --------------------------
__global__ __launch_bounds__(128) void gnn_kernel(const float* __restrict__ Wgs, const float* __restrict__ bgs,
                                                  const float* __restrict__ Wgt, const float* __restrict__ bgt)
{
    const int g = blockIdx.x, which = blockIdx.y;   // g in [0,64)
    const float* fe  = which ? g_fet : g_fes;
    const float* W   = which ? Wgt : Wgs;
    const float* bias= which ? bgt : bgs;
    float* fg        = which ? g_fgt : g_fgs;
    const int c = threadIdx.x;
    __shared__ float h2[4][2*CC];
    __shared__ float red[CC];
    __shared__ int nb[4][KNNK];

    if (c < 32) {
        int rr = c >> 3, q = c & 7;
        nb[rr][q] = g_nbr[((size_t)which*BB + g*4 + rr)*KNNK + q];
    }
    __syncthreads();

    #pragma unroll
    for (int rr = 0; rr < 4; rr++) {
        h2[rr][c] = fe[(size_t)(g*4 + rr)*CC + c];
        float agg = 0.f;
        #pragma unroll
        for (int q = 0; q < KNNK; q++) agg += fe[(size_t)nb[rr][q]*CC + c];
        h2[rr][CC + c] = agg * (1.0f/KNNK);
    }
    __syncthreads();

    float acc[4];
    float bv = bias[c];
    #pragma unroll
    for (int rr = 0; rr < 4; rr++) acc[rr] = bv;
    #pragma unroll 4
    for (int r = 0; r < 2*CC; r++) {
        float wv = W[(size_t)r*CC + c];
        #pragma unroll
        for (int rr = 0; rr < 4; rr++) acc[rr] += h2[rr][r]*wv;
    }

    for (int rr = 0; rr < 4; rr++) {
        red[c] = acc[rr]*acc[rr]; __syncthreads();
        for (int off = 64; off > 0; off >>= 1) { if (c < off) red[c] += red[c+off]; __syncthreads(); }
        float inv = rsqrtf(red[0]); __syncthreads();
        fg[(size_t)(g*4 + rr)*CC + c] = acc[rr]*inv;
    }
}

// ---------------- smooth + positive logits ---------------------------------
__device__ __forceinline__ float breduce128(float v, float* red, int c)
{
    red[c] = v; __syncthreads();
    for (int off = 64; off > 0; off >>= 1) { if (c < off) red[c] += red[c+off]; __syncthreads(); }
    float r = red[0]; __syncthreads();
    return r;
}

__global__ __launch_bounds__(128) void smooth_pos_kernel(const int* __restrict__ idx,
        const float* __restrict__ mem_l, const float* __restrict__ mem_ab)
{
    const int b = blockIdx.x, c = threadIdx.x;
    __shared__ float red[CC];
    const int id = idx[b];
    float ml  = mem_l [(size_t)id*CC + c];
    float mab = mem_ab[(size_t)id*CC + c];
    float fes = g_fes[(size_t)b*CC + c], fet = g_fet[(size_t)b*CC + c];
    float fgs = g_fgs[(size_t)b*CC + c], fgt = g_fgt[(size_t)b*CC + c];

    float sgs = ml *0.75f + fgs*0.25f;
    float sgt = mab*0.75f + fgt*0.25f;
    sgs *= rsqrtf(breduce128(sgs*sgs, red, c));
    sgt *= rsqrtf(breduce128(sgt*sgt, red, c));

    float ls = breduce128(mab*fes, red, c);
    float lt = breduce128(ml *fet, red, c);
    float gs = breduce128(sgt*fgs, red, c);
    float gt = breduce128(sgs*fgt, red, c);
    if (c == 0) {
        g_pos[0*BB+b] = ls; g_pos[1*BB+b] = lt;
        g_pos[2*BB+b] = gs; g_pos[3*BB+b] = gt;
    }
}

// ---------------- heavy kernel: gathered dual-GEMV + fixed-shift LSE --------
// 8 lanes per row, 4 rows per warp iteration. grid (256, 2).
__global__ __launch_bounds__(256) void neg_kernel(const int* __restrict__ cidx,
        const float* __restrict__ mem_l, const float* __restrict__ mem_ab)
{
    const int b = blockIdx.x, bank = blockIdx.y;
    const float* mem = bank ? mem_ab : mem_l;
    const float* v1p = (bank ? g_fet : g_fes) + (size_t)b*CC;
    const float* v2p = (bank ? g_fgt : g_fgs) + (size_t)b*CC;
    const int t = threadIdx.x, w = t >> 5, lane = t & 31;
    const int j = lane & 7;     // segment within row (16 floats each)
    const int r = lane >> 3;    // row within group of 4

    // query slices: float4 index j + 8*i, i = 0..3
    float4 a1[4], a2[4];
    #pragma unroll
    for (int i = 0; i < 4; i++) {
        a1[i] = ((const float4*)v1p)[j + 8*i];
        a2[i] = ((const float4*)v2p)[j + 8*i];
    }

    const int* ci = cidx + (size_t)b*KK + w*(KK/8);   // 512 indices per warp

    float s1 = 0.f, s2 = 0.f;
    #pragma unroll 2
    for (int it = 0; it < 128; it++) {
        int row = ci[it*4 + r];                     // 8-way broadcast within group
        const float4* mp = (const float4*)(mem + (size_t)row*CC);
        float d1 = 0.f, d2 = 0.f;
        #pragma unroll
        for (int i = 0; i < 4; i++) {
            float4 x = mp[j + 8*i];
            d1 += x.x*a1[i].x + x.y*a1[i].y + x.z*a1[i].z + x.w*a1[i].w;
            d2 += x.x*a2[i].x + x.y*a2[i].y + x.z*a2[i].z + x.w*a2[i].w;
        }
        // reduce over j (8 lanes): after this every lane in a group holds full dot
        #pragma unroll
        for (int o = 4; o; o >>= 1) {
            d1 += __shfl_xor_sync(0xffffffffu, d1, o);
            d2 += __shfl_xor_sync(0xffffffffu, d2, o);
        }
        s1 += __expf(fmaf(d1, INV_T, -LSE_SHIFT));   // identical across the 8 lanes of a group
        s2 += __expf(fmaf(d2, INV_T, -LSE_SHIFT));
    }
    // full warp reduce; each group contributed 8 identical copies -> scale by 1/8 (exact)
    #pragma unroll
    for (int o = 16; o; o >>= 1) {
        s1 += __shfl_xor_sync(0xffffffffu, s1, o);
        s2 += __shfl_xor_sync(0xffffffffu, s2, o);
    }
    s1 *= 0.125f; s2 *= 0.125f;

    __shared__ float ss1[8], ss2[8];
    if (lane == 0) { ss1[w] = s1; ss2[w] = s2; }
    __syncthreads();
    if (t == 0) {
        const int st1 = bank;       // 0:ls, 1:lt
        const int st2 = 2 + bank;   // 2:gs, 3:gt
        float p1 = g_pos[st1*BB + b] * INV_T;
        float p2 = g_pos[st2*BB + b] * INV_T;
        float S1 = __expf(p1 - LSE_SHIFT);
        float S2 = __expf(p2 - LSE_SHIFT);
        #pragma unroll
        for (int q = 0; q < 8; q++) { S1 += ss1[q]; S2 += ss2[q]; }
        g_term[st1*BB + b] = LSE_SHIFT + logf(S1) - p1;
        g_term[st2*BB + b] = LSE_SHIFT + logf(S2) - p2;
    }
}

// ---------------- final reduce ----------------------------------------------
__global__ __launch_bounds__(256) void final_kernel(float* __restrict__ out)
{
    const int t = threadIdx.x;
    __shared__ float red[256];
    float v = g_term[t] + g_term[BB + t] + g_term[2*BB + t] + g_term[3*BB + t];
    red[t] = v; __syncthreads();
    for (int off = 128; off > 0; off >>= 1) { if (t < off) red[t] += red[t+off]; __syncthreads(); }
    if (t == 0) out[0] = red[0] * (1.0f/BB);
}

// ---------------- launch -----------------------------------------------------
extern "C" void kernel_launch(void* const* d_in, const int* in_sizes, int n_in,
                              void* d_out, int out_size)
{
    const float* f_s   = (const float*)d_in[1];
    const float* l_s   = (const float*)d_in[2];
    const float* f_t   = (const float*)d_in[3];
    const float* l_t   = (const float*)d_in[4];
    const int*   idx   = (const int*)  d_in[5];
    const int*   cidx  = (const int*)  d_in[6];
    const float* W_es  = (const float*)d_in[7];
    const float* b_es  = (const float*)d_in[8];
    const float* W_et  = (const float*)d_in[9];
    const float* b_et  = (const float*)d_in[10];
    const float* W_gs  = (const float*)d_in[11];
    const float* b_gs  = (const float*)d_in[12];
    const float* W_gt  = (const float*)d_in[13];
    const float* b_gt  = (const float*)d_in[14];
    const float* mem_l = (const float*)d_in[15];
    const float* mem_ab= (const float*)d_in[16];
    float* out = (float*)d_out;

    embed_kernel<1024, 8><<<BB/8, 128>>>(f_s, W_es, b_es);   // -> g_fes
    embed_kernel<2048, 4><<<BB/4, 128>>>(f_t, W_et, b_et);   // -> g_fet
    soft_kernel<<<dim3(BB, 2), 128>>>(l_s, l_t);             // -> g_u
    knn_kernel<<<dim3(BB, 2), 128>>>();                      // -> g_nbr
    gnn_kernel<<<dim3(BB/4, 2), 128>>>(W_gs, b_gs, W_gt, b_gt); // -> g_fgs/g_fgt
    smooth_pos_kernel<<<BB, 128>>>(idx, mem_l, mem_ab);      // -> g_pos
    neg_kernel<<<dim3(BB, 2), 256>>>(cidx, mem_l, mem_ab);   // -> g_term
    final_kernel<<<1, 256>>>(out);
}